// round 15
// baseline (speedup 1.0000x reference)
#include <cuda_runtime.h>
#include <cuda_fp16.h>
#include <math.h>

#define Bc 4
#define Nc 5
#define Cc 64
#define Hc 96
#define Wc 288
#define HWc (Hc * Wc)

// DECAY_WEIGHTS = softmax([1.0, 0.5])
#define W0c 0.6224593312018546f
#define W1c 0.3775406687981454f

// score tiling
#define SPX 16
#define SCG 16
#define SCPT 4

// fuse tiling
#define GPX 32

__device__ float g_mask[Bc * HWc];
__device__ float g_dmask[Bc * HWc];
// fp16 channel-last copy of x0: layout ((b*Nc+n)*HWc + p)*Cc + c
__device__ __half g_x0h[(size_t)Bc * Nc * HWc * Cc];

// ---------------------------------------------------------------------------
// Kernel A: per-pixel confidence -> binary mask (fp32, unchanged math),
// plus fp16 channel-last transposed copy of x0 (smem-staged).
// Epilogue reduction parallelized across 8 warps (one per (f,k) pair).
// ---------------------------------------------------------------------------
__global__ __launch_bounds__(SPX * SCG, 6)
void score_kernel(const float* __restrict__ x0, const float* __restrict__ x1,
                  const float* __restrict__ mlp_w, const float* __restrict__ mlp_b) {
    __shared__ float  sm_ss[2][4][SCG][SPX];   // 8 KB
    __shared__ float  sm_mm[2][4][SCG][SPX];   // 8 KB
    __shared__ float  sm_rs[2][4][SPX];        // reduced ss
    __shared__ float  sm_rm[2][4][SPX];        // reduced mm
    __shared__ float4 sm_t[Nc][SPX][SCG + 1];  // 21.25 KB staging (f32)

    int tx = threadIdx.x;          // pixel in tile
    int ty = threadIdx.y;          // channel group
    int p0 = blockIdx.x * SPX;
    int p  = p0 + tx;
    int b  = blockIdx.y;
    int c0 = ty * SCPT;
    int tid = ty * SPX + tx;

    float w[SCPT];
    #pragma unroll
    for (int cc = 0; cc < SCPT; cc++) w[cc] = __ldg(mlp_w + c0 + cc);

    #pragma unroll
    for (int f = 0; f < 2; f++) {
        const float* xf = (f == 0) ? x0 : x1;
        const float* base = xf + (size_t)b * Nc * Cc * HWc + (size_t)c0 * HWc + p;

        float e[SCPT];
        #pragma unroll
        for (int cc = 0; cc < SCPT; cc++) e[cc] = base[(size_t)cc * HWc];
        if (f == 0) sm_t[0][tx][ty] = make_float4(e[0], e[1], e[2], e[3]);

        #pragma unroll
        for (int k = 0; k < 4; k++) {
            const float* nb = base + (size_t)(k + 1) * Cc * HWc;
            float nv[SCPT];
            #pragma unroll
            for (int cc = 0; cc < SCPT; cc++) nv[cc] = nb[(size_t)cc * HWc];
            if (f == 0) sm_t[k + 1][tx][ty] = make_float4(nv[0], nv[1], nv[2], nv[3]);
            float ss = 0.f, mm = 0.f;
            #pragma unroll
            for (int cc = 0; cc < SCPT; cc++) {
                ss = fmaf(e[cc], nv[cc], ss);
                mm = fmaf(w[cc], nv[cc], mm);
            }
            sm_ss[f][k][ty][tx] = ss;
            sm_mm[f][k][ty][tx] = mm;
        }
    }
    __syncthreads();

    // ---- fp16 transposed writeout: 1280 uint2-slots (4 halves each), 5/thread ----
    {
        uint2* xh = reinterpret_cast<uint2*>(g_x0h) + (size_t)b * Nc * HWc * (Cc / 4);
        #pragma unroll
        for (int i = 0; i < Nc; i++) {
            int g  = tid + i * (SPX * SCG);
            int n  = g >> 8;           // / 256
            int r  = g & 255;
            int px = r >> 4;
            int q  = r & 15;           // channel quad
            float4 val = sm_t[n][px][q];
            __half2 h0 = __floats2half2_rn(val.x, val.y);
            __half2 h1 = __floats2half2_rn(val.z, val.w);
            uint2 packed;
            packed.x = *reinterpret_cast<unsigned*>(&h0);
            packed.y = *reinterpret_cast<unsigned*>(&h1);
            xh[((size_t)n * HWc + p0 + px) * (Cc / 4) + q] = packed;
        }
    }

    // ---- stage 1: warp w (w<8) reduces (f,k)=w over channel groups ----
    {
        int wid  = tid >> 5;
        int lane = tid & 31;
        if (wid < 8) {
            int f  = wid >> 2;
            int k  = wid & 3;
            int px = lane & 15;
            int doMM = lane >> 4;
            const float* src = doMM ? &sm_mm[f][k][0][px] : &sm_ss[f][k][0][px];
            float acc = 0.f;
            #pragma unroll
            for (int cg = 0; cg < SCG; cg++) acc += src[cg * SPX];
            if (doMM) sm_rm[f][k][px] = acc;
            else      sm_rs[f][k][px] = acc;
        }
    }
    __syncthreads();

    // ---- stage 2: 16 threads finish the confidence math ----
    if (tid < SPX) {
        float bb = __ldg(mlp_b);
        float conf = 0.f;
        const float dw[2] = {W0c, W1c};
        #pragma unroll
        for (int f = 0; f < 2; f++) {
            float s[4], m[4];
            #pragma unroll
            for (int k = 0; k < 4; k++) {
                s[k] = sm_rs[f][k][tid] * 0.125f;
                m[k] = sm_rm[f][k][tid];
            }
            float mx = fmaxf(fmaxf(s[0], s[1]), fmaxf(s[2], s[3]));
            float sum = 0.f, acc = 0.f;
            #pragma unroll
            for (int k = 0; k < 4; k++) {
                float e2 = expf(s[k] - mx);
                sum += e2;
                acc = fmaf(e2, m[k], acc);
            }
            float z = acc / sum + bb;
            conf += dw[f] / (1.f + expf(-z));
        }
        g_mask[b * HWc + p0 + tid] = (conf > 0.5f) ? 1.0f : 0.0f;
    }
}

// ---------------------------------------------------------------------------
// Kernel B: 3x3 max dilation (SAME)
// ---------------------------------------------------------------------------
__global__ void dilate_kernel() {
    int p = blockIdx.x * blockDim.x + threadIdx.x;
    int b = blockIdx.y;
    if (p >= HWc) return;
    int i = p / Wc, j = p % Wc;
    float m = 0.f;
    #pragma unroll
    for (int di = -1; di <= 1; di++) {
        int ii = i + di;
        if (ii < 0 || ii >= Hc) continue;
        #pragma unroll
        for (int dj = -1; dj <= 1; dj++) {
            int jj = j + dj;
            if (jj < 0 || jj >= Wc) continue;
            m = fmaxf(m, g_mask[b * HWc + ii * Wc + jj]);
        }
    }
    g_dmask[b * HWc + p] = m;
}

// ---------------------------------------------------------------------------
// Kernel C: warp + fusion from fp16 channel-last copy (R11 body).
//   Thetas computed inline from pt (no separate theta kernel).
// ---------------------------------------------------------------------------
__global__ __launch_bounds__(512, 3)
void fuse_kernel(const float* __restrict__ pt, float* __restrict__ out) {
    __shared__ int2   sm_ti[Nc][GPX];
    __shared__ float4 sm_tw[Nc][GPX];
    __shared__ float  sm_o[Cc][GPX + 1];

    int tid = threadIdx.x;
    int b   = blockIdx.y;
    int p0  = blockIdx.x * GPX;

    // ---- tap precompute: one thread per (frame, pixel); theta inline ----
    if (tid < Nc * GPX) {
        int n  = tid >> 5;
        int l  = tid & 31;
        int pp = p0 + l;
        int i = pp / Wc, j = pp - i * Wc;
        float gx = -1.f + 2.f * (float)j / (float)(Wc - 1);
        float gy = -1.f + 2.f * (float)i / (float)(Hc - 1);

        const float* P = pt + ((size_t)(b * Nc + 0) * Nc + n) * 16;
        float th0 = __ldg(P + 0);
        float th1 = __ldg(P + 1) * ((float)Hc / (float)Wc);
        float th2 = __ldg(P + 3) / (4.0f * 0.4f * (float)Wc) * 2.0f;
        float th3 = __ldg(P + 4) * ((float)Wc / (float)Hc);
        float th4 = __ldg(P + 5);
        float th5 = __ldg(P + 7) / (4.0f * 0.4f * (float)Hc) * 2.0f;

        float g0 = fmaf(th0, gx, fmaf(th1, gy, th2));
        float g1 = fmaf(th3, gx, fmaf(th4, gy, th5));
        float pxf = (g0 + 1.f) * 0.5f * (float)(Wc - 1);
        float pyf = (g1 + 1.f) * 0.5f * (float)(Hc - 1);
        float x0f = floorf(pxf), y0f = floorf(pyf);
        float wx = pxf - x0f, wy = pyf - y0f;
        int xi = (int)x0f, yi = (int)y0f;

        int r0 = min(max(yi, 0), Hc - 1) * Wc;
        int r1 = min(max(yi + 1, 0), Hc - 1) * Wc;
        float wy0 = (yi >= 0 && yi <= Hc - 1) ? (1.f - wy) : 0.f;
        float wy1 = (yi + 1 >= 0 && yi + 1 <= Hc - 1) ? wy : 0.f;

        int bx = min(max(xi, 0), Wc - 2);
        int sh = xi - bx;
        float ax0, ax1;
        if (sh == 0)        { ax0 = 1.f - wx; ax1 = wx;       }
        else if (sh == -1)  { ax0 = wx;       ax1 = 0.f;      }
        else if (sh == 1)   { ax0 = 0.f;      ax1 = 1.f - wx; }
        else                { ax0 = 0.f;      ax1 = 0.f;      }

        float m00 = 1.f, m01 = 1.f, m10 = 1.f, m11 = 1.f;
        if (n > 0) {
            const float* dm = g_dmask + b * HWc;
            m00 = dm[r0 + bx]; m01 = dm[r0 + bx + 1];
            m10 = dm[r1 + bx]; m11 = dm[r1 + bx + 1];
        }

        sm_ti[n][l] = make_int2(r0 + bx, r1 + bx);
        sm_tw[n][l] = make_float4(ax0 * wy0 * m00, ax1 * wy0 * m01,
                                  ax0 * wy1 * m10, ax1 * wy1 * m11);
    }
    __syncthreads();

    int wrp  = tid >> 5;
    int lane = tid & 31;
    int lpx  = wrp * 2 + (lane >> 4);   // local pixel 0..31
    int cg   = lane & 15;               // channel quad, c0 = 4*cg

    const uint2* xh = reinterpret_cast<const uint2*>(g_x0h)
                    + (size_t)b * Nc * HWc * (Cc / 4) + cg;

    float2 v[Nc][2];   // 4 channels as 2x float2
    float  s[Nc];
    #pragma unroll
    for (int k = 0; k < Nc; k++) {
        int2   ti = sm_ti[k][lpx];
        float4 tw = sm_tw[k][lpx];
        const uint2* fb = xh + (size_t)k * HWc * (Cc / 4);
        uint2 q0 = __ldg(fb + (size_t)ti.x * (Cc / 4));
        uint2 q1 = __ldg(fb + (size_t)(ti.x + 1) * (Cc / 4));
        uint2 q2 = __ldg(fb + (size_t)ti.y * (Cc / 4));
        uint2 q3 = __ldg(fb + (size_t)(ti.y + 1) * (Cc / 4));

        float2 t0a = __half22float2(*reinterpret_cast<__half2*>(&q0.x));
        float2 t0b = __half22float2(*reinterpret_cast<__half2*>(&q0.y));
        float2 t1a = __half22float2(*reinterpret_cast<__half2*>(&q1.x));
        float2 t1b = __half22float2(*reinterpret_cast<__half2*>(&q1.y));
        float2 t2a = __half22float2(*reinterpret_cast<__half2*>(&q2.x));
        float2 t2b = __half22float2(*reinterpret_cast<__half2*>(&q2.y));
        float2 t3a = __half22float2(*reinterpret_cast<__half2*>(&q3.x));
        float2 t3b = __half22float2(*reinterpret_cast<__half2*>(&q3.y));

        float2 va, vb;
        va.x = fmaf(tw.x, t0a.x, fmaf(tw.y, t1a.x, fmaf(tw.z, t2a.x, tw.w * t3a.x)));
        va.y = fmaf(tw.x, t0a.y, fmaf(tw.y, t1a.y, fmaf(tw.z, t2a.y, tw.w * t3a.y)));
        vb.x = fmaf(tw.x, t0b.x, fmaf(tw.y, t1b.x, fmaf(tw.z, t2b.x, tw.w * t3b.x)));
        vb.y = fmaf(tw.x, t0b.y, fmaf(tw.y, t1b.y, fmaf(tw.z, t2b.y, tw.w * t3b.y)));
        v[k][0] = va;
        v[k][1] = vb;

        float d = fmaf(v[0][0].x, va.x, fmaf(v[0][0].y, va.y,
                  fmaf(v[0][1].x, vb.x, v[0][1].y * vb.y)));
        d += __shfl_xor_sync(0xffffffffu, d, 1);
        d += __shfl_xor_sync(0xffffffffu, d, 2);
        d += __shfl_xor_sync(0xffffffffu, d, 4);
        d += __shfl_xor_sync(0xffffffffu, d, 8);
        s[k] = d * 0.125f;
    }

    // softmax over 5
    float mx = s[0];
    #pragma unroll
    for (int k = 1; k < Nc; k++) mx = fmaxf(mx, s[k]);
    float a[Nc], sum = 0.f;
    #pragma unroll
    for (int k = 0; k < Nc; k++) { a[k] = __expf(s[k] - mx); sum += a[k]; }
    float inv = 1.f / sum;

    float o0 = 0.f, o1 = 0.f, o2 = 0.f, o3 = 0.f;
    #pragma unroll
    for (int k = 0; k < Nc; k++) {
        o0 = fmaf(a[k], v[k][0].x, o0);
        o1 = fmaf(a[k], v[k][0].y, o1);
        o2 = fmaf(a[k], v[k][1].x, o2);
        o3 = fmaf(a[k], v[k][1].y, o3);
    }

    sm_o[4 * cg + 0][lpx] = o0 * inv;
    sm_o[4 * cg + 1][lpx] = o1 * inv;
    sm_o[4 * cg + 2][lpx] = o2 * inv;
    sm_o[4 * cg + 3][lpx] = o3 * inv;
    __syncthreads();

    // coalesced writeout: 2048 floats, 4 per thread; warp = 32 px of channel c
    float* ob = out + (size_t)b * Cc * HWc + p0;
    #pragma unroll
    for (int i = 0; i < 4; i++) {
        int g  = tid + i * 512;
        int c  = g >> 5;
        int px = g & 31;
        ob[(size_t)c * HWc + px] = sm_o[c][px];
    }
}

// ---------------------------------------------------------------------------
// Launch
// ---------------------------------------------------------------------------
extern "C" void kernel_launch(void* const* d_in, const int* in_sizes, int n_in,
                              void* d_out, int out_size) {
    const float* x0    = (const float*)d_in[0];
    const float* x1    = (const float*)d_in[1];
    const float* pt    = (const float*)d_in[2];
    const float* mlp_w = (const float*)d_in[3];
    const float* mlp_b = (const float*)d_in[4];
    float* out = (float*)d_out;

    dim3 blkS(SPX, SCG);
    dim3 gridS(HWc / SPX, Bc);
    score_kernel<<<gridS, blkS>>>(x0, x1, mlp_w, mlp_b);

    dim3 gridB((HWc + 255) / 256, Bc);
    dilate_kernel<<<gridB, 256>>>();

    dim3 gridF(HWc / GPX, Bc);
    fuse_kernel<<<gridF, 512>>>(pt, out);
}

// round 17
// speedup vs baseline: 1.2854x; 1.2854x over previous
#include <cuda_runtime.h>
#include <cuda_fp16.h>
#include <math.h>

#define Bc 4
#define Nc 5
#define Cc 64
#define Hc 96
#define Wc 288
#define HWc (Hc * Wc)

// DECAY_WEIGHTS = softmax([1.0, 0.5])
#define W0c 0.6224593312018546f
#define W1c 0.3775406687981454f

// score tiling
#define SPX 16
#define SCG 16
#define SCPT 4

// fuse tiling
#define GPX 32

__device__ float g_mask[Bc * HWc];
__device__ float g_dmask[Bc * HWc];
// fp16 channel-last copy of x0: layout ((b*Nc+n)*HWc + p)*Cc + c
__device__ __half g_x0h[(size_t)Bc * Nc * HWc * Cc];

// ---------------------------------------------------------------------------
// Kernel A: per-pixel confidence -> binary mask (fp32, unchanged math),
// plus fp16 channel-last transposed copy of x0 (smem-staged).
// EXACT R11 configuration (best measured: ~66us).
// ---------------------------------------------------------------------------
__global__ __launch_bounds__(SPX * SCG)
void score_kernel(const float* __restrict__ x0, const float* __restrict__ x1,
                  const float* __restrict__ mlp_w, const float* __restrict__ mlp_b) {
    __shared__ float  sm_ss[2][4][SCG][SPX];   // 8 KB
    __shared__ float  sm_mm[2][4][SCG][SPX];   // 8 KB
    __shared__ float4 sm_t[Nc][SPX][SCG + 1];  // 21.25 KB staging (f32)

    int tx = threadIdx.x;          // pixel in tile
    int ty = threadIdx.y;          // channel group
    int p0 = blockIdx.x * SPX;
    int p  = p0 + tx;
    int b  = blockIdx.y;
    int c0 = ty * SCPT;
    int tid = ty * SPX + tx;

    float w[SCPT];
    #pragma unroll
    for (int cc = 0; cc < SCPT; cc++) w[cc] = __ldg(mlp_w + c0 + cc);

    #pragma unroll
    for (int f = 0; f < 2; f++) {
        const float* xf = (f == 0) ? x0 : x1;
        const float* base = xf + (size_t)b * Nc * Cc * HWc + (size_t)c0 * HWc + p;

        float e[SCPT];
        #pragma unroll
        for (int cc = 0; cc < SCPT; cc++) e[cc] = base[(size_t)cc * HWc];
        if (f == 0) sm_t[0][tx][ty] = make_float4(e[0], e[1], e[2], e[3]);

        #pragma unroll
        for (int k = 0; k < 4; k++) {
            const float* nb = base + (size_t)(k + 1) * Cc * HWc;
            float nv[SCPT];
            #pragma unroll
            for (int cc = 0; cc < SCPT; cc++) nv[cc] = nb[(size_t)cc * HWc];
            if (f == 0) sm_t[k + 1][tx][ty] = make_float4(nv[0], nv[1], nv[2], nv[3]);
            float ss = 0.f, mm = 0.f;
            #pragma unroll
            for (int cc = 0; cc < SCPT; cc++) {
                ss = fmaf(e[cc], nv[cc], ss);
                mm = fmaf(w[cc], nv[cc], mm);
            }
            sm_ss[f][k][ty][tx] = ss;
            sm_mm[f][k][ty][tx] = mm;
        }
    }
    __syncthreads();

    // ---- fp16 transposed writeout: 1280 uint2-slots (4 halves each), 5/thread ----
    {
        uint2* xh = reinterpret_cast<uint2*>(g_x0h) + (size_t)b * Nc * HWc * (Cc / 4);
        #pragma unroll
        for (int i = 0; i < Nc; i++) {
            int g  = tid + i * (SPX * SCG);
            int n  = g >> 8;           // / 256
            int r  = g & 255;
            int px = r >> 4;
            int q  = r & 15;           // channel quad
            float4 val = sm_t[n][px][q];
            __half2 h0 = __floats2half2_rn(val.x, val.y);
            __half2 h1 = __floats2half2_rn(val.z, val.w);
            uint2 packed;
            packed.x = *reinterpret_cast<unsigned*>(&h0);
            packed.y = *reinterpret_cast<unsigned*>(&h1);
            xh[((size_t)n * HWc + p0 + px) * (Cc / 4) + q] = packed;
        }
    }

    if (ty == 0) {
        float bb = __ldg(mlp_b);
        float conf = 0.f;
        const float dw[2] = {W0c, W1c};
        #pragma unroll
        for (int f = 0; f < 2; f++) {
            float s[4], m[4];
            #pragma unroll
            for (int k = 0; k < 4; k++) {
                float ss = 0.f, mm = 0.f;
                #pragma unroll
                for (int cg = 0; cg < SCG; cg++) {
                    ss += sm_ss[f][k][cg][tx];
                    mm += sm_mm[f][k][cg][tx];
                }
                s[k] = ss * 0.125f;
                m[k] = mm;
            }
            float mx = fmaxf(fmaxf(s[0], s[1]), fmaxf(s[2], s[3]));
            float sum = 0.f, acc = 0.f;
            #pragma unroll
            for (int k = 0; k < 4; k++) {
                float e2 = expf(s[k] - mx);
                sum += e2;
                acc = fmaf(e2, m[k], acc);
            }
            float z = acc / sum + bb;
            conf += dw[f] / (1.f + expf(-z));
        }
        g_mask[b * HWc + p] = (conf > 0.5f) ? 1.0f : 0.0f;
    }
}

// ---------------------------------------------------------------------------
// Kernel B: 3x3 max dilation (SAME)
// ---------------------------------------------------------------------------
__global__ void dilate_kernel() {
    int p = blockIdx.x * blockDim.x + threadIdx.x;
    int b = blockIdx.y;
    if (p >= HWc) return;
    int i = p / Wc, j = p % Wc;
    float m = 0.f;
    #pragma unroll
    for (int di = -1; di <= 1; di++) {
        int ii = i + di;
        if (ii < 0 || ii >= Hc) continue;
        #pragma unroll
        for (int dj = -1; dj <= 1; dj++) {
            int jj = j + dj;
            if (jj < 0 || jj >= Wc) continue;
            m = fmaxf(m, g_mask[b * HWc + ii * Wc + jj]);
        }
    }
    g_dmask[b * HWc + p] = m;
}

// ---------------------------------------------------------------------------
// Kernel C: warp + fusion from fp16 channel-last copy (R11 body),
//   thetas computed inline from pt (no separate theta kernel).
// ---------------------------------------------------------------------------
__global__ __launch_bounds__(512, 3)
void fuse_kernel(const float* __restrict__ pt, float* __restrict__ out) {
    __shared__ int2   sm_ti[Nc][GPX];
    __shared__ float4 sm_tw[Nc][GPX];
    __shared__ float  sm_o[Cc][GPX + 1];

    int tid = threadIdx.x;
    int b   = blockIdx.y;
    int p0  = blockIdx.x * GPX;

    // ---- tap precompute: one thread per (frame, pixel); theta inline ----
    if (tid < Nc * GPX) {
        int n  = tid >> 5;
        int l  = tid & 31;
        int pp = p0 + l;
        int i = pp / Wc, j = pp - i * Wc;
        float gx = -1.f + 2.f * (float)j / (float)(Wc - 1);
        float gy = -1.f + 2.f * (float)i / (float)(Hc - 1);

        const float* P = pt + ((size_t)(b * Nc + 0) * Nc + n) * 16;
        float th0 = __ldg(P + 0);
        float th1 = __ldg(P + 1) * ((float)Hc / (float)Wc);
        float th2 = __ldg(P + 3) / (4.0f * 0.4f * (float)Wc) * 2.0f;
        float th3 = __ldg(P + 4) * ((float)Wc / (float)Hc);
        float th4 = __ldg(P + 5);
        float th5 = __ldg(P + 7) / (4.0f * 0.4f * (float)Hc) * 2.0f;

        float g0 = fmaf(th0, gx, fmaf(th1, gy, th2));
        float g1 = fmaf(th3, gx, fmaf(th4, gy, th5));
        float pxf = (g0 + 1.f) * 0.5f * (float)(Wc - 1);
        float pyf = (g1 + 1.f) * 0.5f * (float)(Hc - 1);
        float x0f = floorf(pxf), y0f = floorf(pyf);
        float wx = pxf - x0f, wy = pyf - y0f;
        int xi = (int)x0f, yi = (int)y0f;

        int r0 = min(max(yi, 0), Hc - 1) * Wc;
        int r1 = min(max(yi + 1, 0), Hc - 1) * Wc;
        float wy0 = (yi >= 0 && yi <= Hc - 1) ? (1.f - wy) : 0.f;
        float wy1 = (yi + 1 >= 0 && yi + 1 <= Hc - 1) ? wy : 0.f;

        int bx = min(max(xi, 0), Wc - 2);
        int sh = xi - bx;
        float ax0, ax1;
        if (sh == 0)        { ax0 = 1.f - wx; ax1 = wx;       }
        else if (sh == -1)  { ax0 = wx;       ax1 = 0.f;      }
        else if (sh == 1)   { ax0 = 0.f;      ax1 = 1.f - wx; }
        else                { ax0 = 0.f;      ax1 = 0.f;      }

        float m00 = 1.f, m01 = 1.f, m10 = 1.f, m11 = 1.f;
        if (n > 0) {
            const float* dm = g_dmask + b * HWc;
            m00 = dm[r0 + bx]; m01 = dm[r0 + bx + 1];
            m10 = dm[r1 + bx]; m11 = dm[r1 + bx + 1];
        }

        sm_ti[n][l] = make_int2(r0 + bx, r1 + bx);
        sm_tw[n][l] = make_float4(ax0 * wy0 * m00, ax1 * wy0 * m01,
                                  ax0 * wy1 * m10, ax1 * wy1 * m11);
    }
    __syncthreads();

    int wrp  = tid >> 5;
    int lane = tid & 31;
    int lpx  = wrp * 2 + (lane >> 4);   // local pixel 0..31
    int cg   = lane & 15;               // channel quad, c0 = 4*cg

    const uint2* xh = reinterpret_cast<const uint2*>(g_x0h)
                    + (size_t)b * Nc * HWc * (Cc / 4) + cg;

    float2 v[Nc][2];   // 4 channels as 2x float2
    float  s[Nc];
    #pragma unroll
    for (int k = 0; k < Nc; k++) {
        int2   ti = sm_ti[k][lpx];
        float4 tw = sm_tw[k][lpx];
        const uint2* fb = xh + (size_t)k * HWc * (Cc / 4);
        uint2 q0 = __ldg(fb + (size_t)ti.x * (Cc / 4));
        uint2 q1 = __ldg(fb + (size_t)(ti.x + 1) * (Cc / 4));
        uint2 q2 = __ldg(fb + (size_t)ti.y * (Cc / 4));
        uint2 q3 = __ldg(fb + (size_t)(ti.y + 1) * (Cc / 4));

        float2 t0a = __half22float2(*reinterpret_cast<__half2*>(&q0.x));
        float2 t0b = __half22float2(*reinterpret_cast<__half2*>(&q0.y));
        float2 t1a = __half22float2(*reinterpret_cast<__half2*>(&q1.x));
        float2 t1b = __half22float2(*reinterpret_cast<__half2*>(&q1.y));
        float2 t2a = __half22float2(*reinterpret_cast<__half2*>(&q2.x));
        float2 t2b = __half22float2(*reinterpret_cast<__half2*>(&q2.y));
        float2 t3a = __half22float2(*reinterpret_cast<__half2*>(&q3.x));
        float2 t3b = __half22float2(*reinterpret_cast<__half2*>(&q3.y));

        float2 va, vb;
        va.x = fmaf(tw.x, t0a.x, fmaf(tw.y, t1a.x, fmaf(tw.z, t2a.x, tw.w * t3a.x)));
        va.y = fmaf(tw.x, t0a.y, fmaf(tw.y, t1a.y, fmaf(tw.z, t2a.y, tw.w * t3a.y)));
        vb.x = fmaf(tw.x, t0b.x, fmaf(tw.y, t1b.x, fmaf(tw.z, t2b.x, tw.w * t3b.x)));
        vb.y = fmaf(tw.x, t0b.y, fmaf(tw.y, t1b.y, fmaf(tw.z, t2b.y, tw.w * t3b.y)));
        v[k][0] = va;
        v[k][1] = vb;

        float d = fmaf(v[0][0].x, va.x, fmaf(v[0][0].y, va.y,
                  fmaf(v[0][1].x, vb.x, v[0][1].y * vb.y)));
        d += __shfl_xor_sync(0xffffffffu, d, 1);
        d += __shfl_xor_sync(0xffffffffu, d, 2);
        d += __shfl_xor_sync(0xffffffffu, d, 4);
        d += __shfl_xor_sync(0xffffffffu, d, 8);
        s[k] = d * 0.125f;
    }

    // softmax over 5
    float mx = s[0];
    #pragma unroll
    for (int k = 1; k < Nc; k++) mx = fmaxf(mx, s[k]);
    float a[Nc], sum = 0.f;
    #pragma unroll
    for (int k = 0; k < Nc; k++) { a[k] = __expf(s[k] - mx); sum += a[k]; }
    float inv = 1.f / sum;

    float o0 = 0.f, o1 = 0.f, o2 = 0.f, o3 = 0.f;
    #pragma unroll
    for (int k = 0; k < Nc; k++) {
        o0 = fmaf(a[k], v[k][0].x, o0);
        o1 = fmaf(a[k], v[k][0].y, o1);
        o2 = fmaf(a[k], v[k][1].x, o2);
        o3 = fmaf(a[k], v[k][1].y, o3);
    }

    sm_o[4 * cg + 0][lpx] = o0 * inv;
    sm_o[4 * cg + 1][lpx] = o1 * inv;
    sm_o[4 * cg + 2][lpx] = o2 * inv;
    sm_o[4 * cg + 3][lpx] = o3 * inv;
    __syncthreads();

    // coalesced writeout: 2048 floats, 4 per thread; warp = 32 px of channel c
    float* ob = out + (size_t)b * Cc * HWc + p0;
    #pragma unroll
    for (int i = 0; i < 4; i++) {
        int g  = tid + i * 512;
        int c  = g >> 5;
        int px = g & 31;
        ob[(size_t)c * HWc + px] = sm_o[c][px];
    }
}

// ---------------------------------------------------------------------------
// Launch
// ---------------------------------------------------------------------------
extern "C" void kernel_launch(void* const* d_in, const int* in_sizes, int n_in,
                              void* d_out, int out_size) {
    const float* x0    = (const float*)d_in[0];
    const float* x1    = (const float*)d_in[1];
    const float* pt    = (const float*)d_in[2];
    const float* mlp_w = (const float*)d_in[3];
    const float* mlp_b = (const float*)d_in[4];
    float* out = (float*)d_out;

    dim3 blkS(SPX, SCG);
    dim3 gridS(HWc / SPX, Bc);
    score_kernel<<<gridS, blkS>>>(x0, x1, mlp_w, mlp_b);

    dim3 gridB((HWc + 255) / 256, Bc);
    dilate_kernel<<<gridB, 256>>>();

    dim3 gridF(HWc / GPX, Bc);
    fuse_kernel<<<gridF, 512>>>(pt, out);
}